// round 1
// baseline (speedup 1.0000x reference)
#include <cuda_runtime.h>
#include <math_constants.h>

// Problem constants (fixed by dataset)
#define N_FEAT 6272      // 8 * 28 * 28
#define M_BANK 30000
#define D_DIM  128
#define BATCH  8
#define PH     28
#define PW     28
#define IMG    224

// GEMM tiling
#define BM 64
#define BN 64
#define MSPLIT 4
#define NTILES ((M_BANK + BN - 1) / BN)   // 469
#define SMEM_FLOATS (D_DIM*BM + D_DIM*BN + BN)
#define SMEM_BYTES  (SMEM_FLOATS * 4)     // 65792

// Scratch (no cudaMalloc allowed)
__device__ float        g_m2[M_BANK];
__device__ float        g_f2[N_FEAT];
__device__ unsigned int g_nn[N_FEAT];     // order-preserving float keys
__device__ float        g_patch[N_FEAT];

// ---- order-preserving float <-> uint map (for atomicMin on distances) ----
__device__ __forceinline__ unsigned int fkey(float f) {
    unsigned int b = __float_as_uint(f);
    return (b & 0x80000000u) ? ~b : (b | 0x80000000u);
}
__device__ __forceinline__ float fdecode(unsigned int k) {
    unsigned int b = (k & 0x80000000u) ? (k ^ 0x80000000u) : ~k;
    return __uint_as_float(b);
}

// ---- prep: squared norms of memory rows + feature rows; init nn keys ----
__global__ void k_prep(const float* __restrict__ feat,
                       const float* __restrict__ mem) {
    int w    = (blockIdx.x * blockDim.x + threadIdx.x) >> 5;  // warp id
    int lane = threadIdx.x & 31;
    if (w < M_BANK) {
        const float* r = mem + (size_t)w * D_DIM;
        float s = 0.f;
        #pragma unroll
        for (int j = 0; j < 4; j++) { float v = r[lane + 32 * j]; s = fmaf(v, v, s); }
        #pragma unroll
        for (int o = 16; o; o >>= 1) s += __shfl_xor_sync(0xffffffffu, s, o);
        if (lane == 0) g_m2[w] = s;
    } else {
        int w2 = w - M_BANK;
        if (w2 < N_FEAT) {
            const float* r = feat + (size_t)w2 * D_DIM;
            float s = 0.f;
            #pragma unroll
            for (int j = 0; j < 4; j++) { float v = r[lane + 32 * j]; s = fmaf(v, v, s); }
            #pragma unroll
            for (int o = 16; o; o >>= 1) s += __shfl_xor_sync(0xffffffffu, s, o);
            if (lane == 0) {
                g_f2[w2] = s;
                g_nn[w2] = 0xFF800000u;   // fkey(+inf)
            }
        }
    }
}

// ---- main: fused 64x64-tiled GEMM + row-min of (||m||^2 - 2 f.m) ----
__global__ void __launch_bounds__(256, 3)
k_nnmin(const float* __restrict__ feat, const float* __restrict__ mem) {
    extern __shared__ float smem[];
    float* As  = smem;                       // [D_DIM][BM]  (K-major)
    float* Bs  = smem + D_DIM * BM;          // [D_DIM][BN]  (K-major)
    float* m2s = smem + D_DIM * (BM + BN);   // [BN]

    const int tid = threadIdx.x;
    const int ty  = tid >> 4;   // 0..15  -> rows ty*4 .. ty*4+3
    const int tx  = tid & 15;   // 0..15  -> cols tx*4 .. tx*4+3
    const int r0  = blockIdx.x * BM;

    // Load A tile once: As[k][r]  (transposed store, conflict-free)
    {
        int r  = tid & 63;
        int k0 = (tid >> 6) * 4;
        const float* fr = feat + (size_t)(r0 + r) * D_DIM;
        #pragma unroll
        for (int kk = 0; kk < 8; kk++) {
            int k = k0 + kk * 16;
            float4 v = *reinterpret_cast<const float4*>(fr + k);
            As[(k + 0) * BM + r] = v.x;
            As[(k + 1) * BM + r] = v.y;
            As[(k + 2) * BM + r] = v.z;
            As[(k + 3) * BM + r] = v.w;
        }
    }

    float minv[4] = {CUDART_INF_F, CUDART_INF_F, CUDART_INF_F, CUDART_INF_F};

    const int t0 = ( blockIdx.y      * NTILES) / MSPLIT;
    const int t1 = ((blockIdx.y + 1) * NTILES) / MSPLIT;

    for (int t = t0; t < t1; t++) {
        const int c0 = t * BN;
        __syncthreads();
        // Load B tile: Bs[k][c]
        {
            int c  = tid & 63;
            int k0 = (tid >> 6) * 4;
            int gc = c0 + c;
            bool ok = gc < M_BANK;
            const float* mr = mem + (size_t)(ok ? gc : 0) * D_DIM;
            #pragma unroll
            for (int kk = 0; kk < 8; kk++) {
                int k = k0 + kk * 16;
                float4 v = ok ? *reinterpret_cast<const float4*>(mr + k)
                              : make_float4(0.f, 0.f, 0.f, 0.f);
                Bs[(k + 0) * BN + c] = v.x;
                Bs[(k + 1) * BN + c] = v.y;
                Bs[(k + 2) * BN + c] = v.z;
                Bs[(k + 3) * BN + c] = v.w;
            }
            if (tid < BN) {
                int g = c0 + tid;
                m2s[tid] = (g < M_BANK) ? g_m2[g] : CUDART_INF_F;
            }
        }
        __syncthreads();

        float acc[4][4] = {};
        #pragma unroll 8
        for (int k = 0; k < D_DIM; k++) {
            float4 a = *reinterpret_cast<const float4*>(&As[k * BM + ty * 4]);
            float4 b = *reinterpret_cast<const float4*>(&Bs[k * BN + tx * 4]);
            acc[0][0] = fmaf(a.x, b.x, acc[0][0]);
            acc[0][1] = fmaf(a.x, b.y, acc[0][1]);
            acc[0][2] = fmaf(a.x, b.z, acc[0][2]);
            acc[0][3] = fmaf(a.x, b.w, acc[0][3]);
            acc[1][0] = fmaf(a.y, b.x, acc[1][0]);
            acc[1][1] = fmaf(a.y, b.y, acc[1][1]);
            acc[1][2] = fmaf(a.y, b.z, acc[1][2]);
            acc[1][3] = fmaf(a.y, b.w, acc[1][3]);
            acc[2][0] = fmaf(a.z, b.x, acc[2][0]);
            acc[2][1] = fmaf(a.z, b.y, acc[2][1]);
            acc[2][2] = fmaf(a.z, b.z, acc[2][2]);
            acc[2][3] = fmaf(a.z, b.w, acc[2][3]);
            acc[3][0] = fmaf(a.w, b.x, acc[3][0]);
            acc[3][1] = fmaf(a.w, b.y, acc[3][1]);
            acc[3][2] = fmaf(a.w, b.z, acc[3][2]);
            acc[3][3] = fmaf(a.w, b.w, acc[3][3]);
        }
        #pragma unroll
        for (int i = 0; i < 4; i++) {
            #pragma unroll
            for (int j = 0; j < 4; j++) {
                float d = fmaf(-2.f, acc[i][j], m2s[tx * 4 + j]);
                minv[i] = fminf(minv[i], d);
            }
        }
    }

    // Reduce min across tx (16 threads share the same 4 rows)
    #pragma unroll
    for (int i = 0; i < 4; i++) {
        float v = minv[i];
        #pragma unroll
        for (int o = 8; o; o >>= 1) v = fminf(v, __shfl_xor_sync(0xffffffffu, v, o));
        if (tx == 0) atomicMin(&g_nn[r0 + ty * 4 + i], fkey(v));
    }
}

// ---- finalize: patch score = min(||m||^2 - 2f.m) + ||f||^2 ----
__global__ void k_final() {
    int i = blockIdx.x * blockDim.x + threadIdx.x;
    if (i < N_FEAT) g_patch[i] = fdecode(g_nn[i]) + g_f2[i];
}

// ---- per-batch max over 784 patch scores ----
__global__ void k_scores(float* __restrict__ out) {
    __shared__ float red[256];
    int b = blockIdx.x;
    float m = -CUDART_INF_F;
    for (int t = threadIdx.x; t < PH * PW; t += 256)
        m = fmaxf(m, g_patch[b * PH * PW + t]);
    red[threadIdx.x] = m;
    __syncthreads();
    for (int s = 128; s; s >>= 1) {
        if (threadIdx.x < s) red[threadIdx.x] = fmaxf(red[threadIdx.x], red[threadIdx.x + s]);
        __syncthreads();
    }
    if (threadIdx.x == 0) out[b] = red[0];
}

// ---- bilinear upsample 28x28 -> 224x224, half-pixel (align_corners=False) ----
__global__ void k_upsample(float* __restrict__ up) {
    int idx = blockIdx.x * blockDim.x + threadIdx.x;
    if (idx >= BATCH * IMG * IMG) return;
    int x = idx % IMG;
    int y = (idx / IMG) % IMG;
    int b = idx / (IMG * IMG);

    const float scale = (float)PH / (float)IMG;   // 0.125
    float sy = (y + 0.5f) * scale - 0.5f;
    float sx = (x + 0.5f) * scale - 0.5f;
    int   y0 = (int)floorf(sy);
    int   x0 = (int)floorf(sx);
    float wy = sy - (float)y0;
    float wx = sx - (float)x0;
    int y0c = min(max(y0, 0), PH - 1);
    int y1c = min(max(y0 + 1, 0), PH - 1);
    int x0c = min(max(x0, 0), PW - 1);
    int x1c = min(max(x0 + 1, 0), PW - 1);

    const float* p = g_patch + b * PH * PW;
    float v00 = p[y0c * PW + x0c];
    float v01 = p[y0c * PW + x1c];
    float v10 = p[y1c * PW + x0c];
    float v11 = p[y1c * PW + x1c];
    float v0 = v00 + (v01 - v00) * wx;
    float v1 = v10 + (v11 - v10) * wx;
    up[idx] = v0 + (v1 - v0) * wy;
}

extern "C" void kernel_launch(void* const* d_in, const int* in_sizes, int n_in,
                              void* d_out, int out_size) {
    const float* feat = (const float*)d_in[0];
    const float* mem  = (const float*)d_in[1];
    float* out    = (float*)d_out;
    float* scores = out;                                      // [8]
    float* up     = out + (out_size - BATCH * IMG * IMG);     // [8,224,224]

    cudaFuncSetAttribute(k_nnmin, cudaFuncAttributeMaxDynamicSharedMemorySize, SMEM_BYTES);

    // 1) norms + nn init (one warp per row)
    {
        long long warps = (long long)M_BANK + N_FEAT;
        long long thr   = warps * 32;
        int blocks = (int)((thr + 255) / 256);
        k_prep<<<blocks, 256>>>(feat, mem);
    }
    // 2) fused distance GEMM + row-min
    {
        dim3 grid(N_FEAT / BM, MSPLIT);
        k_nnmin<<<grid, 256, SMEM_BYTES>>>(feat, mem);
    }
    // 3) finalize patch scores
    k_final<<<(N_FEAT + 255) / 256, 256>>>();
    // 4) image scores (max per batch)
    k_scores<<<BATCH, 256>>>(scores);
    // 5) bilinear upsample
    k_upsample<<<(BATCH * IMG * IMG + 255) / 256, 256>>>(up);
}

// round 3
// speedup vs baseline: 4.5193x; 4.5193x over previous
#include <cuda_runtime.h>
#include <cuda_bf16.h>
#include <math_constants.h>
#include <cstdint>

// ---------------- problem constants ----------------
#define N_FEAT 6272      // 8 * 28 * 28
#define M_BANK 30000
#define M_PAD  30720     // padded to 480 tiles of 64
#define D_DIM  128
#define KP     384       // 3 * D (hi|hi|lo vs hi|lo|hi split)
#define BATCH  8
#define PH     28
#define PW     28
#define IMG    224

// ---------------- GEMM tiling ----------------
#define TILE_M 128
#define TILE_N 64
#define M_TILES 49               // 6272 / 128
#define SPLIT  3
#define TILES_PER_SPLIT 160      // 480 / 3
#define ROW_PITCH 768            // KP * 2 bytes
#define NCHUNK 48                // KP*2/16 16-byte chunks per row

// ---------------- SMEM layout ----------------
#define SMEM_M2   0                          // 2 x 64 floats = 512 B
#define SMEM_A    1024                       // 128 x 768 B = 96 KB
#define SMEM_B0   (1024 + TILE_M * ROW_PITCH)   // 99328
#define BBUF_BYTES (TILE_N * ROW_PITCH)         // 49152
#define SMEM_TOTAL (SMEM_B0 + 2 * BBUF_BYTES)   // 197632

// ---------------- device scratch ----------------
__device__ __align__(16) __nv_bfloat16 g_Ap[(size_t)N_FEAT * KP];
__device__ __align__(16) __nv_bfloat16 g_Bp[(size_t)M_PAD * KP];
__device__ float        g_m2p[M_PAD];
__device__ float        g_f2[N_FEAT];
__device__ unsigned int g_nn[N_FEAT];
__device__ float        g_patch[N_FEAT];

// ---------------- asm helpers ----------------
__device__ __forceinline__ uint32_t smem_to_u32(const void* p) {
    uint32_t a;
    asm("{ .reg .u64 t; cvta.to.shared.u64 t, %1; cvt.u32.u64 %0, t; }" : "=r"(a) : "l"(p));
    return a;
}
#define CP_ASYNC16(dst, src) \
    asm volatile("cp.async.cg.shared.global [%0], [%1], 16;" :: "r"(dst), "l"(src) : "memory")
#define CP_COMMIT() asm volatile("cp.async.commit_group;" ::: "memory")
#define CP_WAIT(n)  asm volatile("cp.async.wait_group %0;" :: "n"(n) : "memory")
#define LDSM4(r, addr) \
    asm volatile("ldmatrix.sync.aligned.m8n8.x4.shared.b16 {%0,%1,%2,%3}, [%4];" \
        : "=r"((r)[0]), "=r"((r)[1]), "=r"((r)[2]), "=r"((r)[3]) : "r"(addr))
#define MMA16816(c, a, bb0, bb1) \
    asm volatile("mma.sync.aligned.m16n8k16.row.col.f32.bf16.bf16.f32 " \
        "{%0,%1,%2,%3}, {%4,%5,%6,%7}, {%8,%9}, {%0,%1,%2,%3};" \
        : "+f"((c)[0]), "+f"((c)[1]), "+f"((c)[2]), "+f"((c)[3]) \
        : "r"((a)[0]), "r"((a)[1]), "r"((a)[2]), "r"((a)[3]), "r"(bb0), "r"(bb1))

// ---- order-preserving float <-> uint map ----
__device__ __forceinline__ unsigned int fkey(float f) {
    unsigned int b = __float_as_uint(f);
    return (b & 0x80000000u) ? ~b : (b | 0x80000000u);
}
__device__ __forceinline__ float fdecode(unsigned int k) {
    unsigned int b = (k & 0x80000000u) ? (k ^ 0x80000000u) : ~k;
    return __uint_as_float(b);
}

// ---------------- prep: bf16 hi/lo split + norms ----------------
// A' sections: [hi | hi | lo], B' sections: [hi | lo | hi]
__global__ void k_prep(const float* __restrict__ feat, const float* __restrict__ mem) {
    int w    = (blockIdx.x * blockDim.x + threadIdx.x) >> 5;
    int lane = threadIdx.x & 31;
    int k0   = lane * 4;
    if (w < M_PAD) {
        size_t base = (size_t)w * KP;
        if (w < M_BANK) {
            float4 v = *reinterpret_cast<const float4*>(mem + (size_t)w * D_DIM + k0);
            __nv_bfloat16 h0 = __float2bfloat16(v.x), h1 = __float2bfloat16(v.y);
            __nv_bfloat16 h2 = __float2bfloat16(v.z), h3 = __float2bfloat16(v.w);
            __nv_bfloat16 l0 = __float2bfloat16(v.x - __bfloat162float(h0));
            __nv_bfloat16 l1 = __float2bfloat16(v.y - __bfloat162float(h1));
            __nv_bfloat16 l2 = __float2bfloat16(v.z - __bfloat162float(h2));
            __nv_bfloat16 l3 = __float2bfloat16(v.w - __bfloat162float(h3));
            __nv_bfloat162 hA = __halves2bfloat162(h0, h1), hB = __halves2bfloat162(h2, h3);
            __nv_bfloat162 lA = __halves2bfloat162(l0, l1), lB = __halves2bfloat162(l2, l3);
            *reinterpret_cast<__nv_bfloat162*>(g_Bp + base + k0)           = hA;
            *reinterpret_cast<__nv_bfloat162*>(g_Bp + base + k0 + 2)       = hB;
            *reinterpret_cast<__nv_bfloat162*>(g_Bp + base + 128 + k0)     = lA;
            *reinterpret_cast<__nv_bfloat162*>(g_Bp + base + 128 + k0 + 2) = lB;
            *reinterpret_cast<__nv_bfloat162*>(g_Bp + base + 256 + k0)     = hA;
            *reinterpret_cast<__nv_bfloat162*>(g_Bp + base + 256 + k0 + 2) = hB;
            float s = v.x*v.x + v.y*v.y + v.z*v.z + v.w*v.w;
            #pragma unroll
            for (int o = 16; o; o >>= 1) s += __shfl_xor_sync(0xffffffffu, s, o);
            if (lane == 0) g_m2p[w] = s;
        } else {
            __nv_bfloat162 z = __halves2bfloat162(__float2bfloat16(0.f), __float2bfloat16(0.f));
            #pragma unroll
            for (int sec = 0; sec < 3; sec++) {
                *reinterpret_cast<__nv_bfloat162*>(g_Bp + base + sec*128 + k0)     = z;
                *reinterpret_cast<__nv_bfloat162*>(g_Bp + base + sec*128 + k0 + 2) = z;
            }
            if (lane == 0) g_m2p[w] = CUDART_INF_F;
        }
    } else {
        int w2 = w - M_PAD;
        if (w2 < N_FEAT) {
            size_t base = (size_t)w2 * KP;
            float4 v = *reinterpret_cast<const float4*>(feat + (size_t)w2 * D_DIM + k0);
            __nv_bfloat16 h0 = __float2bfloat16(v.x), h1 = __float2bfloat16(v.y);
            __nv_bfloat16 h2 = __float2bfloat16(v.z), h3 = __float2bfloat16(v.w);
            __nv_bfloat16 l0 = __float2bfloat16(v.x - __bfloat162float(h0));
            __nv_bfloat16 l1 = __float2bfloat16(v.y - __bfloat162float(h1));
            __nv_bfloat16 l2 = __float2bfloat16(v.z - __bfloat162float(h2));
            __nv_bfloat16 l3 = __float2bfloat16(v.w - __bfloat162float(h3));
            __nv_bfloat162 hA = __halves2bfloat162(h0, h1), hB = __halves2bfloat162(h2, h3);
            __nv_bfloat162 lA = __halves2bfloat162(l0, l1), lB = __halves2bfloat162(l2, l3);
            *reinterpret_cast<__nv_bfloat162*>(g_Ap + base + k0)           = hA;
            *reinterpret_cast<__nv_bfloat162*>(g_Ap + base + k0 + 2)       = hB;
            *reinterpret_cast<__nv_bfloat162*>(g_Ap + base + 128 + k0)     = hA;
            *reinterpret_cast<__nv_bfloat162*>(g_Ap + base + 128 + k0 + 2) = hB;
            *reinterpret_cast<__nv_bfloat162*>(g_Ap + base + 256 + k0)     = lA;
            *reinterpret_cast<__nv_bfloat162*>(g_Ap + base + 256 + k0 + 2) = lB;
            float s = v.x*v.x + v.y*v.y + v.z*v.z + v.w*v.w;
            #pragma unroll
            for (int o = 16; o; o >>= 1) s += __shfl_xor_sync(0xffffffffu, s, o);
            if (lane == 0) {
                g_f2[w2] = s;
                g_nn[w2] = 0xFF800000u;  // fkey(+inf)
            }
        }
    }
}

// B-tile (+ m2 slice) prefetch via cp.async into swizzled SMEM
__device__ __forceinline__ void load_B_tile(uint32_t sbB, uint32_t sbM2, int tileIdx, int tid) {
    const size_t c0 = (size_t)tileIdx * TILE_N;
    #pragma unroll
    for (int i = 0; i < 12; i++) {
        int idx = tid + i * 256;       // 0..3071
        int row = idx / NCHUNK;
        int c   = idx % NCHUNK;
        uint32_t dst = sbB + row * ROW_PITCH + ((uint32_t)(c ^ (row & 7)) << 4);
        const void* src = g_Bp + (c0 + row) * KP + c * 8;
        CP_ASYNC16(dst, src);
    }
    if (tid < 16) {
        const void* src = g_m2p + c0 + tid * 4;
        CP_ASYNC16(sbM2 + tid * 16, src);
    }
}

// ---------------- main HMMA GEMM + row-min ----------------
// 256 threads = 8 warps in 4(m) x 2(n) grid; warp tile 32x32.
__global__ void __launch_bounds__(256, 1)
k_gemm() {
    extern __shared__ __align__(1024) char smem[];
    const uint32_t sb = smem_to_u32(smem);
    const uint32_t sA = sb + SMEM_A;
    const int tid  = threadIdx.x;
    const int lane = tid & 31;
    const int wid  = tid >> 5;
    const int wm   = wid >> 1;   // 0..3
    const int wn   = wid & 1;    // 0..1
    const int r0   = blockIdx.x * TILE_M;
    const int tile0 = blockIdx.y * TILES_PER_SPLIT;

    // ---- resident A tile: 6144 16B chunks, swizzled ----
    #pragma unroll
    for (int i = 0; i < 24; i++) {
        int idx = tid + i * 256;
        int row = idx / NCHUNK;
        int c   = idx % NCHUNK;
        uint32_t dst = sA + row * ROW_PITCH + ((uint32_t)(c ^ (row & 7)) << 4);
        const void* src = g_Ap + (size_t)(r0 + row) * KP + c * 8;
        CP_ASYNC16(dst, src);
    }
    // B tile 0 into buffer 0 (same commit group as A)
    load_B_tile(sb + SMEM_B0, sb + SMEM_M2, tile0, tid);
    CP_COMMIT();

    // ---- per-thread ldmatrix invariants ----
    // A: threads 0-15 rows m0..15 @k-lo chunk, 16-31 same rows @k-hi chunk
    uint32_t aBase[2], aRx[2];
    #pragma unroll
    for (int mt = 0; mt < 2; mt++) {
        int row = wm * 32 + mt * 16 + (lane & 15);
        aBase[mt] = sA + row * ROW_PITCH;
        aRx[mt]   = (uint32_t)(row & 7);
    }
    const uint32_t aHi = (uint32_t)(lane >> 4);          // 0/1
    // B: t0-7: n0..7 @k-lo; t8-15: n0..7 @k-hi; t16-23: n8..15 @k-lo; t24-31: @k-hi
    uint32_t bOff[2], bRx[2];
    #pragma unroll
    for (int bt = 0; bt < 2; bt++) {
        int n = wn * 32 + bt * 16 + (lane & 7) + ((lane & 16) >> 1);
        bOff[bt] = (uint32_t)(n * ROW_PITCH);
        bRx[bt]  = (uint32_t)(n & 7);
    }
    const uint32_t bHi = (uint32_t)((lane >> 3) & 1);    // 0/1

    float minv[4] = {CUDART_INF_F, CUDART_INF_F, CUDART_INF_F, CUDART_INF_F};

    for (int t = 0; t < TILES_PER_SPLIT; t++) {
        if (t + 1 < TILES_PER_SPLIT) {
            load_B_tile(sb + SMEM_B0 + (uint32_t)((t + 1) & 1) * BBUF_BYTES,
                        sb + SMEM_M2 + (uint32_t)((t + 1) & 1) * 256,
                        tile0 + t + 1, tid);
            CP_COMMIT();
            CP_WAIT(1);
        } else {
            CP_WAIT(0);
        }
        __syncthreads();

        const uint32_t bb = sb + SMEM_B0 + (uint32_t)(t & 1) * BBUF_BYTES;
        float acc[2][4][4] = {};

        #pragma unroll
        for (int ks = 0; ks < 24; ks++) {
            uint32_t a0[4], a1[4], b0[4], b1[4];
            LDSM4(a0, aBase[0] + (((2u * ks + aHi) ^ aRx[0]) << 4));
            LDSM4(a1, aBase[1] + (((2u * ks + aHi) ^ aRx[1]) << 4));
            LDSM4(b0, bb + bOff[0] + (((2u * ks + bHi) ^ bRx[0]) << 4));
            LDSM4(b1, bb + bOff[1] + (((2u * ks + bHi) ^ bRx[1]) << 4));
            MMA16816(acc[0][0], a0, b0[0], b0[1]);
            MMA16816(acc[0][1], a0, b0[2], b0[3]);
            MMA16816(acc[0][2], a0, b1[0], b1[1]);
            MMA16816(acc[0][3], a0, b1[2], b1[3]);
            MMA16816(acc[1][0], a1, b0[0], b0[1]);
            MMA16816(acc[1][1], a1, b0[2], b0[3]);
            MMA16816(acc[1][2], a1, b1[0], b1[1]);
            MMA16816(acc[1][3], a1, b1[2], b1[3]);
        }

        // epilogue: d = m2[c] - 2*dot ; fold into running row min
        const float* m2s = reinterpret_cast<const float*>(smem + SMEM_M2 + (t & 1) * 256);
        #pragma unroll
        for (int nt = 0; nt < 4; nt++) {
            float2 mm = *reinterpret_cast<const float2*>(&m2s[wn * 32 + nt * 8 + (lane & 3) * 2]);
            #pragma unroll
            for (int mt = 0; mt < 2; mt++) {
                float d0 = fmaf(-2.f, acc[mt][nt][0], mm.x);
                float d1 = fmaf(-2.f, acc[mt][nt][1], mm.y);
                float d2 = fmaf(-2.f, acc[mt][nt][2], mm.x);
                float d3 = fmaf(-2.f, acc[mt][nt][3], mm.y);
                minv[mt * 2 + 0] = fminf(minv[mt * 2 + 0], fminf(d0, d1));
                minv[mt * 2 + 1] = fminf(minv[mt * 2 + 1], fminf(d2, d3));
            }
        }
        __syncthreads();
    }

    // reduce across the 4 lanes sharing each row, then atomicMin
    #pragma unroll
    for (int i = 0; i < 4; i++) {
        float v = minv[i];
        v = fminf(v, __shfl_xor_sync(0xffffffffu, v, 1));
        v = fminf(v, __shfl_xor_sync(0xffffffffu, v, 2));
        if ((lane & 3) == 0) {
            int row = r0 + wm * 32 + (i >> 1) * 16 + (i & 1) * 8 + (lane >> 2);
            atomicMin(&g_nn[row], fkey(v));
        }
    }
}

// ---- finalize: patch score = min(||m||^2 - 2 f.m) + ||f||^2 ----
__global__ void k_final() {
    int i = blockIdx.x * blockDim.x + threadIdx.x;
    if (i < N_FEAT) g_patch[i] = fdecode(g_nn[i]) + g_f2[i];
}

// ---- per-batch max over 784 patch scores ----
__global__ void k_scores(float* __restrict__ out) {
    __shared__ float red[256];
    int b = blockIdx.x;
    float m = -CUDART_INF_F;
    for (int t = threadIdx.x; t < PH * PW; t += 256)
        m = fmaxf(m, g_patch[b * PH * PW + t]);
    red[threadIdx.x] = m;
    __syncthreads();
    for (int s = 128; s; s >>= 1) {
        if (threadIdx.x < s) red[threadIdx.x] = fmaxf(red[threadIdx.x], red[threadIdx.x + s]);
        __syncthreads();
    }
    if (threadIdx.x == 0) out[b] = red[0];
}

// ---- bilinear upsample 28x28 -> 224x224, half-pixel ----
__global__ void k_upsample(float* __restrict__ up) {
    int idx = blockIdx.x * blockDim.x + threadIdx.x;
    if (idx >= BATCH * IMG * IMG) return;
    int x = idx % IMG;
    int y = (idx / IMG) % IMG;
    int b = idx / (IMG * IMG);

    const float scale = (float)PH / (float)IMG;
    float sy = (y + 0.5f) * scale - 0.5f;
    float sx = (x + 0.5f) * scale - 0.5f;
    int   y0 = (int)floorf(sy);
    int   x0 = (int)floorf(sx);
    float wy = sy - (float)y0;
    float wx = sx - (float)x0;
    int y0c = min(max(y0, 0), PH - 1);
    int y1c = min(max(y0 + 1, 0), PH - 1);
    int x0c = min(max(x0, 0), PW - 1);
    int x1c = min(max(x0 + 1, 0), PW - 1);

    const float* p = g_patch + b * PH * PW;
    float v00 = p[y0c * PW + x0c];
    float v01 = p[y0c * PW + x1c];
    float v10 = p[y1c * PW + x0c];
    float v11 = p[y1c * PW + x1c];
    float v0 = v00 + (v01 - v00) * wx;
    float v1 = v10 + (v11 - v10) * wx;
    up[idx] = v0 + (v1 - v0) * wy;
}

extern "C" void kernel_launch(void* const* d_in, const int* in_sizes, int n_in,
                              void* d_out, int out_size) {
    const float* feat = (const float*)d_in[0];
    const float* mem  = (const float*)d_in[1];
    float* out    = (float*)d_out;
    float* scores = out;
    float* up     = out + (out_size - BATCH * IMG * IMG);

    static int configured = 0;
    if (!configured) {
        cudaFuncSetAttribute(k_gemm, cudaFuncAttributeMaxDynamicSharedMemorySize, SMEM_TOTAL);
        configured = 1;
    }

    // 1) split/convert + norms (one warp per row)
    {
        long long warps = (long long)M_PAD + N_FEAT;
        int blocks = (int)((warps * 32 + 255) / 256);
        k_prep<<<blocks, 256>>>(feat, mem);
    }
    // 2) HMMA bf16-split GEMM + row-min
    {
        dim3 grid(M_TILES, SPLIT);
        k_gemm<<<grid, 256, SMEM_TOTAL>>>();
    }
    // 3) finalize patch scores
    k_final<<<(N_FEAT + 255) / 256, 256>>>();
    // 4) image scores
    k_scores<<<BATCH, 256>>>(scores);
    // 5) bilinear upsample
    k_upsample<<<(BATCH * IMG * IMG + 255) / 256, 256>>>(up);
}

// round 5
// speedup vs baseline: 12.0101x; 2.6575x over previous
#include <cuda_runtime.h>
#include <cuda_fp16.h>
#include <math_constants.h>
#include <cstdint>

// ---------------- problem constants ----------------
#define N_FEAT 6272      // 8 * 28 * 28
#define M_BANK 30000
#define M_PAD  30720     // 240 tiles of 128
#define D_DIM  128
#define BATCH  8
#define PH     28
#define PW     28
#define IMG    224

// ---------------- GEMM tiling ----------------
#define TILE_M 128
#define TILE_N 128
#define M_TILES 49               // 6272 / 128
#define SPLIT  6
#define TILES_PER_SPLIT 40       // 240 / 6
#define ROW_PITCH 256            // 128 halves * 2 B

// ---------------- SMEM layout ----------------
#define SMEM_M2   0                               // 2 x 128 floats = 1024 B
#define SMEM_A    1024                            // 128 x 256 B = 32 KB
#define SMEM_B0   (1024 + TILE_M * ROW_PITCH)     // 33792
#define BBUF_BYTES (TILE_N * ROW_PITCH)           // 32768
#define SMEM_TOTAL (SMEM_B0 + 2 * BBUF_BYTES)     // 99328

// ---------------- device scratch ----------------
__device__ __align__(16) __half g_Ah[(size_t)N_FEAT * D_DIM];
__device__ __align__(16) __half g_Bh[(size_t)M_PAD * D_DIM];
__device__ float        g_m2p[M_PAD];
__device__ float        g_f2[N_FEAT];
__device__ unsigned int g_nn[N_FEAT];
__device__ float        g_patch[N_FEAT];

// ---------------- asm helpers ----------------
__device__ __forceinline__ uint32_t smem_to_u32(const void* p) {
    uint32_t a;
    asm("{ .reg .u64 t; cvta.to.shared.u64 t, %1; cvt.u32.u64 %0, t; }" : "=r"(a) : "l"(p));
    return a;
}
#define CP_ASYNC16(dst, src) \
    asm volatile("cp.async.cg.shared.global [%0], [%1], 16;" :: "r"(dst), "l"(src) : "memory")
#define CP_COMMIT() asm volatile("cp.async.commit_group;" ::: "memory")
#define CP_WAIT(n)  asm volatile("cp.async.wait_group %0;" :: "n"(n) : "memory")
#define LDSM4(r, addr) \
    asm volatile("ldmatrix.sync.aligned.m8n8.x4.shared.b16 {%0,%1,%2,%3}, [%4];" \
        : "=r"((r)[0]), "=r"((r)[1]), "=r"((r)[2]), "=r"((r)[3]) : "r"(addr))
#define MMA16816(c, a, bb0, bb1) \
    asm volatile("mma.sync.aligned.m16n8k16.row.col.f32.f16.f16.f32 " \
        "{%0,%1,%2,%3}, {%4,%5,%6,%7}, {%8,%9}, {%0,%1,%2,%3};" \
        : "+f"((c)[0]), "+f"((c)[1]), "+f"((c)[2]), "+f"((c)[3]) \
        : "r"((a)[0]), "r"((a)[1]), "r"((a)[2]), "r"((a)[3]), "r"(bb0), "r"(bb1))

// ---- order-preserving float <-> uint map ----
__device__ __forceinline__ unsigned int fkey(float f) {
    unsigned int b = __float_as_uint(f);
    return (b & 0x80000000u) ? ~b : (b | 0x80000000u);
}
__device__ __forceinline__ float fdecode(unsigned int k) {
    unsigned int b = (k & 0x80000000u) ? (k ^ 0x80000000u) : ~k;
    return __uint_as_float(b);
}

// ---------------- prep: fp16 convert + fp32 norms ----------------
__global__ void k_prep(const float* __restrict__ feat, const float* __restrict__ mem) {
    int w    = (blockIdx.x * blockDim.x + threadIdx.x) >> 5;
    int lane = threadIdx.x & 31;
    int k0   = lane * 4;
    if (w < M_PAD) {
        __half2* dst = reinterpret_cast<__half2*>(g_Bh + (size_t)w * D_DIM + k0);
        if (w < M_BANK) {
            float4 v = *reinterpret_cast<const float4*>(mem + (size_t)w * D_DIM + k0);
            dst[0] = __floats2half2_rn(v.x, v.y);
            dst[1] = __floats2half2_rn(v.z, v.w);
            float s = v.x*v.x + v.y*v.y + v.z*v.z + v.w*v.w;
            #pragma unroll
            for (int o = 16; o; o >>= 1) s += __shfl_xor_sync(0xffffffffu, s, o);
            if (lane == 0) g_m2p[w] = s;
        } else {
            dst[0] = __floats2half2_rn(0.f, 0.f);
            dst[1] = __floats2half2_rn(0.f, 0.f);
            if (lane == 0) g_m2p[w] = CUDART_INF_F;
        }
    } else {
        int w2 = w - M_PAD;
        if (w2 < N_FEAT) {
            float4 v = *reinterpret_cast<const float4*>(feat + (size_t)w2 * D_DIM + k0);
            __half2* dst = reinterpret_cast<__half2*>(g_Ah + (size_t)w2 * D_DIM + k0);
            dst[0] = __floats2half2_rn(v.x, v.y);
            dst[1] = __floats2half2_rn(v.z, v.w);
            float s = v.x*v.x + v.y*v.y + v.z*v.z + v.w*v.w;
            #pragma unroll
            for (int o = 16; o; o >>= 1) s += __shfl_xor_sync(0xffffffffu, s, o);
            if (lane == 0) {
                g_f2[w2] = s;
                g_nn[w2] = 0xFF800000u;  // fkey(+inf)
            }
        }
    }
}

// B-tile (+ m2 slice) prefetch via cp.async into swizzled SMEM
__device__ __forceinline__ void load_B_tile(uint32_t sbB, uint32_t sbM2, int tileIdx, int tid) {
    const size_t c0 = (size_t)tileIdx * TILE_N;
    #pragma unroll
    for (int i = 0; i < 8; i++) {
        int idx = tid + i * 256;        // 0..2047
        int row = idx >> 4;
        int c   = idx & 15;
        uint32_t dst = sbB + row * ROW_PITCH + ((uint32_t)(c ^ (row & 7)) << 4);
        const void* src = g_Bh + (c0 + row) * D_DIM + c * 8;
        CP_ASYNC16(dst, src);
    }
    if (tid < 32) {
        const void* src = g_m2p + c0 + tid * 4;
        CP_ASYNC16(sbM2 + tid * 16, src);
    }
}

// ---------------- main HMMA fp16 GEMM + row-min ----------------
// 256 threads = 8 warps in 4(m) x 2(n) grid; warp tile 32x64; 2 CTAs/SM.
__global__ void __launch_bounds__(256, 2)
k_gemm() {
    extern __shared__ __align__(1024) char smem[];
    const uint32_t sb = smem_to_u32(smem);
    const uint32_t sA = sb + SMEM_A;
    const int tid  = threadIdx.x;
    const int lane = tid & 31;
    const int wid  = tid >> 5;
    const int wm   = wid >> 1;   // 0..3
    const int wn   = wid & 1;    // 0..1
    const int r0   = blockIdx.x * TILE_M;
    const int tile0 = blockIdx.y * TILES_PER_SPLIT;

    // ---- resident A tile: 2048 16B chunks, swizzled ----
    #pragma unroll
    for (int i = 0; i < 8; i++) {
        int idx = tid + i * 256;
        int row = idx >> 4;
        int c   = idx & 15;
        uint32_t dst = sA + row * ROW_PITCH + ((uint32_t)(c ^ (row & 7)) << 4);
        const void* src = g_Ah + (size_t)(r0 + row) * D_DIM + c * 8;
        CP_ASYNC16(dst, src);
    }
    load_B_tile(sb + SMEM_B0, sb + SMEM_M2, tile0, tid);
    CP_COMMIT();

    // ---- per-thread ldmatrix invariants ----
    uint32_t aBase[2], aRx[2];
    #pragma unroll
    for (int mt = 0; mt < 2; mt++) {
        int row = wm * 32 + mt * 16 + (lane & 15);
        aBase[mt] = sA + row * ROW_PITCH;
        aRx[mt]   = (uint32_t)(row & 7);
    }
    const uint32_t aHi = (uint32_t)(lane >> 4);
    uint32_t bOff[4], bRx[4];
    #pragma unroll
    for (int bt = 0; bt < 4; bt++) {
        int n = wn * 64 + bt * 16 + (lane & 7) + ((lane & 16) >> 1);
        bOff[bt] = (uint32_t)(n * ROW_PITCH);
        bRx[bt]  = (uint32_t)(n & 7);
    }
    const uint32_t bHi = (uint32_t)((lane >> 3) & 1);

    float minv[4] = {CUDART_INF_F, CUDART_INF_F, CUDART_INF_F, CUDART_INF_F};

    for (int t = 0; t < TILES_PER_SPLIT; t++) {
        if (t + 1 < TILES_PER_SPLIT) {
            load_B_tile(sb + SMEM_B0 + (uint32_t)((t + 1) & 1) * BBUF_BYTES,
                        sb + SMEM_M2 + (uint32_t)((t + 1) & 1) * 512,
                        tile0 + t + 1, tid);
            CP_COMMIT();
            CP_WAIT(1);
        } else {
            CP_WAIT(0);
        }
        __syncthreads();

        const uint32_t bb = sb + SMEM_B0 + (uint32_t)(t & 1) * BBUF_BYTES;
        float acc[2][8][4] = {};

        #pragma unroll
        for (int ks = 0; ks < 8; ks++) {
            uint32_t a0[4], a1[4], b[4][4];
            LDSM4(a0, aBase[0] + (((2u * ks + aHi) ^ aRx[0]) << 4));
            LDSM4(a1, aBase[1] + (((2u * ks + aHi) ^ aRx[1]) << 4));
            #pragma unroll
            for (int bt = 0; bt < 4; bt++)
                LDSM4(b[bt], bb + bOff[bt] + (((2u * ks + bHi) ^ bRx[bt]) << 4));
            #pragma unroll
            for (int bt = 0; bt < 4; bt++) {
                MMA16816(acc[0][2*bt],   a0, b[bt][0], b[bt][1]);
                MMA16816(acc[0][2*bt+1], a0, b[bt][2], b[bt][3]);
                MMA16816(acc[1][2*bt],   a1, b[bt][0], b[bt][1]);
                MMA16816(acc[1][2*bt+1], a1, b[bt][2], b[bt][3]);
            }
        }

        // epilogue: d = m2[c] - 2*dot ; fold into running row min
        const float* m2s = reinterpret_cast<const float*>(smem + SMEM_M2 + (t & 1) * 512);
        #pragma unroll
        for (int nt = 0; nt < 8; nt++) {
            float2 mm = *reinterpret_cast<const float2*>(&m2s[wn * 64 + nt * 8 + (lane & 3) * 2]);
            #pragma unroll
            for (int mt = 0; mt < 2; mt++) {
                float d0 = fmaf(-2.f, acc[mt][nt][0], mm.x);
                float d1 = fmaf(-2.f, acc[mt][nt][1], mm.y);
                float d2 = fmaf(-2.f, acc[mt][nt][2], mm.x);
                float d3 = fmaf(-2.f, acc[mt][nt][3], mm.y);
                minv[mt * 2 + 0] = fminf(minv[mt * 2 + 0], fminf(d0, d1));
                minv[mt * 2 + 1] = fminf(minv[mt * 2 + 1], fminf(d2, d3));
            }
        }
        __syncthreads();
    }

    // reduce across the 4 lanes sharing each row, then atomicMin
    #pragma unroll
    for (int i = 0; i < 4; i++) {
        float v = minv[i];
        v = fminf(v, __shfl_xor_sync(0xffffffffu, v, 1));
        v = fminf(v, __shfl_xor_sync(0xffffffffu, v, 2));
        if ((lane & 3) == 0) {
            int row = r0 + wm * 32 + (i >> 1) * 16 + (i & 1) * 8 + (lane >> 2);
            atomicMin(&g_nn[row], fkey(v));
        }
    }
}

// ---- merged finalize + per-batch max ----
__global__ void k_scores(float* __restrict__ out) {
    __shared__ float red[256];
    int b = blockIdx.x;
    float m = -CUDART_INF_F;
    for (int t = threadIdx.x; t < PH * PW; t += 256) {
        int i = b * PH * PW + t;
        float p = fdecode(g_nn[i]) + g_f2[i];
        g_patch[i] = p;
        m = fmaxf(m, p);
    }
    red[threadIdx.x] = m;
    __syncthreads();
    for (int s = 128; s; s >>= 1) {
        if (threadIdx.x < s) red[threadIdx.x] = fmaxf(red[threadIdx.x], red[threadIdx.x + s]);
        __syncthreads();
    }
    if (threadIdx.x == 0) out[b] = red[0];
}

// ---- bilinear upsample 28x28 -> 224x224, half-pixel ----
__global__ void k_upsample(float* __restrict__ up) {
    int idx = blockIdx.x * blockDim.x + threadIdx.x;
    if (idx >= BATCH * IMG * IMG) return;
    int x = idx % IMG;
    int y = (idx / IMG) % IMG;
    int b = idx / (IMG * IMG);

    const float scale = (float)PH / (float)IMG;
    float sy = (y + 0.5f) * scale - 0.5f;
    float sx = (x + 0.5f) * scale - 0.5f;
    int   y0 = (int)floorf(sy);
    int   x0 = (int)floorf(sx);
    float wy = sy - (float)y0;
    float wx = sx - (float)x0;
    int y0c = min(max(y0, 0), PH - 1);
    int y1c = min(max(y0 + 1, 0), PH - 1);
    int x0c = min(max(x0, 0), PW - 1);
    int x1c = min(max(x0 + 1, 0), PW - 1);

    const float* p = g_patch + b * PH * PW;
    float v00 = p[y0c * PW + x0c];
    float v01 = p[y0c * PW + x1c];
    float v10 = p[y1c * PW + x0c];
    float v11 = p[y1c * PW + x1c];
    float v0 = v00 + (v01 - v00) * wx;
    float v1 = v10 + (v11 - v10) * wx;
    up[idx] = v0 + (v1 - v0) * wy;
}

extern "C" void kernel_launch(void* const* d_in, const int* in_sizes, int n_in,
                              void* d_out, int out_size) {
    const float* feat = (const float*)d_in[0];
    const float* mem  = (const float*)d_in[1];
    float* out    = (float*)d_out;
    float* scores = out;
    float* up     = out + (out_size - BATCH * IMG * IMG);

    static int configured = 0;
    if (!configured) {
        cudaFuncSetAttribute(k_gemm, cudaFuncAttributeMaxDynamicSharedMemorySize, SMEM_TOTAL);
        configured = 1;
    }

    // 1) fp16 convert + norms (one warp per row)
    {
        long long warps = (long long)M_PAD + N_FEAT;
        int blocks = (int)((warps * 32 + 255) / 256);
        k_prep<<<blocks, 256>>>(feat, mem);
    }
    // 2) fp16 HMMA GEMM + row-min
    {
        dim3 grid(M_TILES, SPLIT);
        k_gemm<<<grid, 256, SMEM_TOTAL>>>();
    }
    // 3) patch scores + image scores
    k_scores<<<BATCH, 256>>>(scores);
    // 4) bilinear upsample
    k_upsample<<<(BATCH * IMG * IMG + 255) / 256, 256>>>(up);
}